// round 1
// baseline (speedup 1.0000x reference)
#include <cuda_runtime.h>
#include <cuda_bf16.h>
#include <cstddef>

// ---------------------------------------------------------------------------
// GridGNNLayer: N=256 nodes, C=32, H=W=64, E=4096 edges, edge_emb=4,
// hidden=64, emb_dim=32, F=2.
// Pipeline:
//   1) k_down      : x[256,32,64,64] -> xd[256,4,32,32]  (2x2 stride-2 conv)
//                    (also zeroes g_agg)
//   2) k_edge      : per-edge fused: gather xd[row],xd[col] -> conv3x3(8->4)
//                    +ReLU -> conv3x3(4->4)+ReLU -> atomicAdd into g_agg[row]
//   3) k_up        : g_agg -> g_up[256,4,64,64] (2x2 stride-2 transposed conv)
//   4) k_conv3x3<36,64,relu>  : concat(x, up) -> g_hidden
//   5) k_conv3x3<64,32>       : g_hidden -> d_out
// ---------------------------------------------------------------------------

#define NNODE 256
#define NEDGE 4096

// scratch (device globals: no runtime allocation allowed)
__device__ float g_xd    [NNODE * 4 * 32 * 32];                 //   4 MB
__device__ float g_agg   [NNODE * 4 * 32 * 32];                 //   4 MB
__device__ float g_up    [NNODE * 4 * 64 * 64];                 //  16 MB
__device__ float g_hidden[(size_t)NNODE * 64 * 64 * 64];        // 268 MB

// ---------------------------------------------------------------------------
// 1) downsample: xd[n,o,p,q] = b[o] + sum_{c,a,b} x[n,c,2p+a,2q+b]*w[o,c,a,b]
//    also zero g_agg (1M floats, exactly 4 per thread)
// ---------------------------------------------------------------------------
__global__ __launch_bounds__(256) void k_down(const float* __restrict__ x,
                                              const float* __restrict__ w,
                                              const float* __restrict__ b) {
    int idx = blockIdx.x * 256 + threadIdx.x;          // over N*32*32 = 262144
    int n = idx >> 10;
    int p = (idx >> 5) & 31;
    int q = idx & 31;

    float acc0 = __ldg(b + 0), acc1 = __ldg(b + 1);
    float acc2 = __ldg(b + 2), acc3 = __ldg(b + 3);

    const float* xp = x + (size_t)n * 32 * 4096 + (2 * p) * 64 + 2 * q;
    #pragma unroll 4
    for (int c = 0; c < 32; ++c) {
        const float* r0 = xp + c * 4096;
        float v00 = r0[0], v01 = r0[1], v10 = r0[64], v11 = r0[65];
        const float* wp = w + ((c << 2));  // w[o,c,a,b]: o*128 + c*4
        acc0 += v00 * __ldg(wp +   0) + v01 * __ldg(wp +   1) + v10 * __ldg(wp +   2) + v11 * __ldg(wp +   3);
        acc1 += v00 * __ldg(wp + 128) + v01 * __ldg(wp + 129) + v10 * __ldg(wp + 130) + v11 * __ldg(wp + 131);
        acc2 += v00 * __ldg(wp + 256) + v01 * __ldg(wp + 257) + v10 * __ldg(wp + 258) + v11 * __ldg(wp + 259);
        acc3 += v00 * __ldg(wp + 384) + v01 * __ldg(wp + 385) + v10 * __ldg(wp + 386) + v11 * __ldg(wp + 387);
    }
    float* op = g_xd + n * 4096 + p * 32 + q;
    op[0]    = acc0; op[1024] = acc1; op[2048] = acc2; op[3072] = acc3;
    // zero agg at the same indices
    float* ap = g_agg + n * 4096 + p * 32 + q;
    ap[0] = 0.f; ap[1024] = 0.f; ap[2048] = 0.f; ap[3072] = 0.f;
}

// ---------------------------------------------------------------------------
// 2) fused edge network + scatter. One block per edge, 256 threads.
//    smem: 8 channels x 34x34 zero-padded tiles (xd[row] ch0-3, xd[col] ch4-7)
//    conv1 results kept in registers, then written back over channels 0-3.
// ---------------------------------------------------------------------------
__global__ __launch_bounds__(256, 1) void k_edge(const int* __restrict__ eidx,
                                                 const float* __restrict__ we1,
                                                 const float* __restrict__ be1,
                                                 const float* __restrict__ we2,
                                                 const float* __restrict__ be2) {
    __shared__ float sIn[8][34][34];   // 36992 B
    const int e   = blockIdx.x;
    const int row = eidx[e];
    const int col = eidx[NEDGE + e];
    const int tid = threadIdx.x;

    float* sflat = &sIn[0][0][0];
    for (int i = tid; i < 8 * 34 * 34; i += 256) sflat[i] = 0.f;
    __syncthreads();
    for (int i = tid; i < 8192; i += 256) {
        int ch = i >> 10;
        int p  = i & 1023;
        int node = (ch < 4) ? row : col;
        sIn[ch][(p >> 5) + 1][(p & 31) + 1] = g_xd[node * 4096 + (ch & 3) * 1024 + p];
    }
    __syncthreads();

    const int o    = tid >> 6;          // output channel 0..3
    const int lane = tid & 63;
    const int ry   = lane >> 1;         // output row 0..31
    const int cx0  = (lane & 1) << 4;   // column base 0 or 16

    // ---- conv1: 8 -> 4, 3x3 SAME, ReLU ----
    float w1[72];
    #pragma unroll
    for (int i = 0; i < 72; ++i) w1[i] = __ldg(we1 + o * 72 + i);
    float acc1[16];
    {
        float bv = __ldg(be1 + o);
        #pragma unroll
        for (int j = 0; j < 16; ++j) acc1[j] = bv;
    }
    #pragma unroll
    for (int ci = 0; ci < 8; ++ci) {
        float a0 = sIn[ci][ry][cx0],     aa1 = sIn[ci][ry + 1][cx0],     a2 = sIn[ci][ry + 2][cx0];
        float c0 = sIn[ci][ry][cx0 + 1], c1  = sIn[ci][ry + 1][cx0 + 1], c2 = sIn[ci][ry + 2][cx0 + 1];
        const float* wc = w1 + ci * 9;
        #pragma unroll
        for (int j = 0; j < 16; ++j) {
            float d0 = sIn[ci][ry][cx0 + 2 + j];
            float d1 = sIn[ci][ry + 1][cx0 + 2 + j];
            float d2 = sIn[ci][ry + 2][cx0 + 2 + j];
            acc1[j] += a0 * wc[0] + c0 * wc[1] + d0 * wc[2]
                     + aa1 * wc[3] + c1 * wc[4] + d1 * wc[5]
                     + a2 * wc[6] + c2 * wc[7] + d2 * wc[8];
            a0 = c0; aa1 = c1; a2 = c2;
            c0 = d0; c1 = d1; c2 = d2;
        }
    }
    __syncthreads();                     // everyone done READING sIn
    #pragma unroll
    for (int j = 0; j < 16; ++j)
        sIn[o][ry + 1][cx0 + 1 + j] = fmaxf(acc1[j], 0.f);
    __syncthreads();

    // ---- conv2: 4 -> 4, 3x3 SAME, ReLU, scatter-add ----
    float w2[36];
    #pragma unroll
    for (int i = 0; i < 36; ++i) w2[i] = __ldg(we2 + o * 36 + i);
    float acc2[16];
    {
        float bv = __ldg(be2 + o);
        #pragma unroll
        for (int j = 0; j < 16; ++j) acc2[j] = bv;
    }
    #pragma unroll
    for (int ci = 0; ci < 4; ++ci) {
        float a0 = sIn[ci][ry][cx0],     aa1 = sIn[ci][ry + 1][cx0],     a2 = sIn[ci][ry + 2][cx0];
        float c0 = sIn[ci][ry][cx0 + 1], c1  = sIn[ci][ry + 1][cx0 + 1], c2 = sIn[ci][ry + 2][cx0 + 1];
        const float* wc = w2 + ci * 9;
        #pragma unroll
        for (int j = 0; j < 16; ++j) {
            float d0 = sIn[ci][ry][cx0 + 2 + j];
            float d1 = sIn[ci][ry + 1][cx0 + 2 + j];
            float d2 = sIn[ci][ry + 2][cx0 + 2 + j];
            acc2[j] += a0 * wc[0] + c0 * wc[1] + d0 * wc[2]
                     + aa1 * wc[3] + c1 * wc[4] + d1 * wc[5]
                     + a2 * wc[6] + c2 * wc[7] + d2 * wc[8];
            a0 = c0; aa1 = c1; a2 = c2;
            c0 = d0; c1 = d1; c2 = d2;
        }
    }
    float* aggp = g_agg + row * 4096 + o * 1024 + ry * 32 + cx0;
    #pragma unroll
    for (int j = 0; j < 16; ++j)
        atomicAdd(aggp + j, fmaxf(acc2[j], 0.f));
}

// ---------------------------------------------------------------------------
// 3) transposed-conv upsample (kernel==stride==2):
//    up[n,o,y,x] = b[o] + sum_c agg[n,c,y/2,x/2] * w_up[c,o,y&1,x&1]
// ---------------------------------------------------------------------------
__global__ __launch_bounds__(256) void k_up(const float* __restrict__ w,
                                            const float* __restrict__ b) {
    int idx = blockIdx.x * 256 + threadIdx.x;   // over 256*4*64*64
    int n   = idx >> 14;
    int rem = idx & 16383;
    int o   = rem >> 12;
    int p   = rem & 4095;
    int y   = p >> 6;
    int xq  = p & 63;
    int i = y >> 1, j = xq >> 1, a = y & 1, bb = xq & 1;
    float v = __ldg(b + o);
    const float* ag = g_agg + n * 4096 + i * 32 + j;
    #pragma unroll
    for (int c = 0; c < 4; ++c)
        v += ag[c * 1024] * __ldg(w + (((c * 4 + o) * 2 + a) * 2 + bb));
    g_up[idx] = v;
}

// ---------------------------------------------------------------------------
// 4/5) direct 3x3 SAME conv, tile 8 rows x 32 cols, each thread owns
//      8 rows x 8 output channels (weights in registers, sliding window).
//      CONCAT: input channels [0,32) from `in` (32ch/n), [32,36) from `in2`.
// ---------------------------------------------------------------------------
template <int CIN, int COUT, bool RELU, bool CONCAT>
__global__ __launch_bounds__(32 * (COUT / 8), 1)
void k_conv3x3(const float* __restrict__ in, const float* __restrict__ in2,
               const float* __restrict__ w, const float* __restrict__ bias,
               float* __restrict__ out) {
    __shared__ float sT[10 * 34];
    const int n   = blockIdx.z;
    const int ty0 = blockIdx.y * 8;
    const int tx0 = blockIdx.x * 32;
    const int tx  = threadIdx.x;
    const int og  = threadIdx.y;
    const int NT  = 32 * (COUT / 8);
    const int tid = og * 32 + tx;

    float acc[8][8];
    #pragma unroll
    for (int r = 0; r < 8; ++r)
        #pragma unroll
        for (int o = 0; o < 8; ++o) acc[r][o] = 0.f;

    for (int c = 0; c < CIN; ++c) {
        const float* src;
        if (CONCAT) {
            src = (c < 32) ? (in  + ((size_t)n * 32 + c) * 4096)
                           : (in2 + ((size_t)n * 4 + (c - 32)) * 4096);
        } else {
            src = in + ((size_t)n * CIN + c) * 4096;
        }
        __syncthreads();   // previous channel's reads done
        for (int i = tid; i < 340; i += NT) {
            int sy = i / 34, sx = i - sy * 34;
            int gy = ty0 + sy - 1, gx = tx0 + sx - 1;
            float v = 0.f;
            if ((unsigned)gy < 64u && (unsigned)gx < 64u) v = __ldg(src + gy * 64 + gx);
            sT[i] = v;
        }
        float wr[8][9];
        {
            const float* wp = w + ((size_t)(og * 8) * CIN + c) * 9;
            #pragma unroll
            for (int o = 0; o < 8; ++o)
                #pragma unroll
                for (int t = 0; t < 9; ++t)
                    wr[o][t] = __ldg(wp + (size_t)o * CIN * 9 + t);
        }
        __syncthreads();

        float r0a = sT[tx], r0b = sT[tx + 1], r0c = sT[tx + 2];
        float r1a = sT[34 + tx], r1b = sT[34 + tx + 1], r1c = sT[34 + tx + 2];
        #pragma unroll
        for (int r = 0; r < 8; ++r) {
            float r2a = sT[(r + 2) * 34 + tx];
            float r2b = sT[(r + 2) * 34 + tx + 1];
            float r2c = sT[(r + 2) * 34 + tx + 2];
            #pragma unroll
            for (int o = 0; o < 8; ++o)
                acc[r][o] += r0a * wr[o][0] + r0b * wr[o][1] + r0c * wr[o][2]
                           + r1a * wr[o][3] + r1b * wr[o][4] + r1c * wr[o][5]
                           + r2a * wr[o][6] + r2b * wr[o][7] + r2c * wr[o][8];
            r0a = r1a; r0b = r1b; r0c = r1c;
            r1a = r2a; r1b = r2b; r1c = r2c;
        }
    }

    #pragma unroll
    for (int o = 0; o < 8; ++o) {
        float bo = __ldg(bias + og * 8 + o);
        #pragma unroll
        for (int r = 0; r < 8; ++r) {
            float v = acc[r][o] + bo;
            if (RELU) v = fmaxf(v, 0.f);
            out[(((size_t)n * COUT + og * 8 + o) * 64 + (ty0 + r)) * 64 + tx0 + tx] = v;
        }
    }
}

// ---------------------------------------------------------------------------
extern "C" void kernel_launch(void* const* d_in, const int* in_sizes, int n_in,
                              void* d_out, int out_size) {
    const float* x      = (const float*)d_in[0];
    const int*   eidx   = (const int*)  d_in[1];
    // d_in[2] = batch_idx (unused)
    const float* w_down = (const float*)d_in[3];
    const float* b_down = (const float*)d_in[4];
    const float* w_e1   = (const float*)d_in[5];
    const float* b_e1   = (const float*)d_in[6];
    const float* w_e2   = (const float*)d_in[7];
    const float* b_e2   = (const float*)d_in[8];
    const float* w_up   = (const float*)d_in[9];
    const float* b_up   = (const float*)d_in[10];
    const float* w_n1   = (const float*)d_in[11];
    const float* b_n1   = (const float*)d_in[12];
    const float* w_n2   = (const float*)d_in[13];
    const float* b_n2   = (const float*)d_in[14];
    float* out = (float*)d_out;

    float *up_ptr = nullptr, *hid_ptr = nullptr;
    cudaGetSymbolAddress((void**)&up_ptr,  g_up);
    cudaGetSymbolAddress((void**)&hid_ptr, g_hidden);

    // 1) downsample (also zeroes g_agg)
    k_down<<<1024, 256>>>(x, w_down, b_down);
    // 2) fused edge network + scatter-add
    k_edge<<<NEDGE, 256>>>(eidx, w_e1, b_e1, w_e2, b_e2);
    // 3) upsample
    k_up<<<16384, 256>>>(w_up, b_up);
    // 4) node conv1: concat(x, up) 36 -> 64, ReLU
    k_conv3x3<36, 64, true, true><<<dim3(2, 8, 256), dim3(32, 8)>>>(
        x, up_ptr, w_n1, b_n1, hid_ptr);
    // 5) node conv2: 64 -> 32
    k_conv3x3<64, 32, false, false><<<dim3(2, 8, 256), dim3(32, 4)>>>(
        hid_ptr, nullptr, w_n2, b_n2, out);
}

// round 2
// speedup vs baseline: 2.1460x; 2.1460x over previous
#include <cuda_runtime.h>
#include <cuda_bf16.h>
#include <cstddef>

// ---------------------------------------------------------------------------
// GridGNNLayer: N=256 nodes, C=32, H=W=64, E=4096 edges, edge_emb=4,
// hidden=64, emb_dim=32, F=2.
//   1) k_down  : x -> xd[256,4,32,32] (2x2 s2 conv), zeroes g_agg
//   2) k_edge  : fused gather->conv3x3(8->4)+ReLU->conv3x3(4->4)+ReLU->scatter
//   3) k_up    : g_agg -> g_up[256,4,64,64] (2x2 s2 transposed conv)
//   4) k_conv3x3<36,64,...>  : concat(x,up) -> g_hidden   (FFMA2 path)
//   5) k_conv3x3<64,32,...>  : g_hidden -> out            (FFMA2 path)
// ---------------------------------------------------------------------------

#define NNODE 256
#define NEDGE 4096

typedef unsigned long long ull;

__device__ float g_xd    [NNODE * 4 * 32 * 32];                 //   4 MB
__device__ float g_agg   [NNODE * 4 * 32 * 32];                 //   4 MB
__device__ float g_up    [NNODE * 4 * 64 * 64];                 //  16 MB
__device__ float g_hidden[(size_t)NNODE * 64 * 64 * 64];        // 268 MB

// ---- packed fp32x2 helpers (sm_100+) --------------------------------------
__device__ __forceinline__ ull pk2(float a, float b) {
    ull r; asm("mov.b64 %0, {%1, %2};" : "=l"(r) : "f"(a), "f"(b)); return r;
}
__device__ __forceinline__ void fma2(ull& d, ull a, ull b) {
    asm("fma.rn.f32x2 %0, %1, %2, %0;" : "+l"(d) : "l"(a), "l"(b));
}
__device__ __forceinline__ void upk2(ull v, float& a, float& b) {
    asm("mov.b64 {%0, %1}, %2;" : "=f"(a), "=f"(b) : "l"(v));
}

// ---------------------------------------------------------------------------
// 1) downsample + zero g_agg
// ---------------------------------------------------------------------------
__global__ __launch_bounds__(256) void k_down(const float* __restrict__ x,
                                              const float* __restrict__ w,
                                              const float* __restrict__ b) {
    int idx = blockIdx.x * 256 + threadIdx.x;          // over N*32*32
    int n = idx >> 10;
    int p = (idx >> 5) & 31;
    int q = idx & 31;

    float acc0 = __ldg(b + 0), acc1 = __ldg(b + 1);
    float acc2 = __ldg(b + 2), acc3 = __ldg(b + 3);

    const float* xp = x + (size_t)n * 32 * 4096 + (2 * p) * 64 + 2 * q;
    #pragma unroll 4
    for (int c = 0; c < 32; ++c) {
        const float* r0 = xp + c * 4096;
        float v00 = r0[0], v01 = r0[1], v10 = r0[64], v11 = r0[65];
        const float* wp = w + (c << 2);
        acc0 += v00 * __ldg(wp +   0) + v01 * __ldg(wp +   1) + v10 * __ldg(wp +   2) + v11 * __ldg(wp +   3);
        acc1 += v00 * __ldg(wp + 128) + v01 * __ldg(wp + 129) + v10 * __ldg(wp + 130) + v11 * __ldg(wp + 131);
        acc2 += v00 * __ldg(wp + 256) + v01 * __ldg(wp + 257) + v10 * __ldg(wp + 258) + v11 * __ldg(wp + 259);
        acc3 += v00 * __ldg(wp + 384) + v01 * __ldg(wp + 385) + v10 * __ldg(wp + 386) + v11 * __ldg(wp + 387);
    }
    float* op = g_xd + n * 4096 + p * 32 + q;
    op[0]    = acc0; op[1024] = acc1; op[2048] = acc2; op[3072] = acc3;
    float* ap = g_agg + n * 4096 + p * 32 + q;
    ap[0] = 0.f; ap[1024] = 0.f; ap[2048] = 0.f; ap[3072] = 0.f;
}

// ---------------------------------------------------------------------------
// 2) fused edge network + scatter (unchanged from R1)
// ---------------------------------------------------------------------------
__global__ __launch_bounds__(256, 1) void k_edge(const int* __restrict__ eidx,
                                                 const float* __restrict__ we1,
                                                 const float* __restrict__ be1,
                                                 const float* __restrict__ we2,
                                                 const float* __restrict__ be2) {
    __shared__ float sIn[8][34][34];
    const int e   = blockIdx.x;
    const int row = eidx[e];
    const int col = eidx[NEDGE + e];
    const int tid = threadIdx.x;

    float* sflat = &sIn[0][0][0];
    for (int i = tid; i < 8 * 34 * 34; i += 256) sflat[i] = 0.f;
    __syncthreads();
    for (int i = tid; i < 8192; i += 256) {
        int ch = i >> 10;
        int p  = i & 1023;
        int node = (ch < 4) ? row : col;
        sIn[ch][(p >> 5) + 1][(p & 31) + 1] = g_xd[node * 4096 + (ch & 3) * 1024 + p];
    }
    __syncthreads();

    const int o    = tid >> 6;
    const int lane = tid & 63;
    const int ry   = lane >> 1;
    const int cx0  = (lane & 1) << 4;

    float w1[72];
    #pragma unroll
    for (int i = 0; i < 72; ++i) w1[i] = __ldg(we1 + o * 72 + i);
    float acc1[16];
    {
        float bv = __ldg(be1 + o);
        #pragma unroll
        for (int j = 0; j < 16; ++j) acc1[j] = bv;
    }
    #pragma unroll
    for (int ci = 0; ci < 8; ++ci) {
        float a0 = sIn[ci][ry][cx0],     aa1 = sIn[ci][ry + 1][cx0],     a2 = sIn[ci][ry + 2][cx0];
        float c0 = sIn[ci][ry][cx0 + 1], c1  = sIn[ci][ry + 1][cx0 + 1], c2 = sIn[ci][ry + 2][cx0 + 1];
        const float* wc = w1 + ci * 9;
        #pragma unroll
        for (int j = 0; j < 16; ++j) {
            float d0 = sIn[ci][ry][cx0 + 2 + j];
            float d1 = sIn[ci][ry + 1][cx0 + 2 + j];
            float d2 = sIn[ci][ry + 2][cx0 + 2 + j];
            acc1[j] += a0 * wc[0] + c0 * wc[1] + d0 * wc[2]
                     + aa1 * wc[3] + c1 * wc[4] + d1 * wc[5]
                     + a2 * wc[6] + c2 * wc[7] + d2 * wc[8];
            a0 = c0; aa1 = c1; a2 = c2;
            c0 = d0; c1 = d1; c2 = d2;
        }
    }
    __syncthreads();
    #pragma unroll
    for (int j = 0; j < 16; ++j)
        sIn[o][ry + 1][cx0 + 1 + j] = fmaxf(acc1[j], 0.f);
    __syncthreads();

    float w2[36];
    #pragma unroll
    for (int i = 0; i < 36; ++i) w2[i] = __ldg(we2 + o * 36 + i);
    float acc2[16];
    {
        float bv = __ldg(be2 + o);
        #pragma unroll
        for (int j = 0; j < 16; ++j) acc2[j] = bv;
    }
    #pragma unroll
    for (int ci = 0; ci < 4; ++ci) {
        float a0 = sIn[ci][ry][cx0],     aa1 = sIn[ci][ry + 1][cx0],     a2 = sIn[ci][ry + 2][cx0];
        float c0 = sIn[ci][ry][cx0 + 1], c1  = sIn[ci][ry + 1][cx0 + 1], c2 = sIn[ci][ry + 2][cx0 + 1];
        const float* wc = w2 + ci * 9;
        #pragma unroll
        for (int j = 0; j < 16; ++j) {
            float d0 = sIn[ci][ry][cx0 + 2 + j];
            float d1 = sIn[ci][ry + 1][cx0 + 2 + j];
            float d2 = sIn[ci][ry + 2][cx0 + 2 + j];
            acc2[j] += a0 * wc[0] + c0 * wc[1] + d0 * wc[2]
                     + aa1 * wc[3] + c1 * wc[4] + d1 * wc[5]
                     + a2 * wc[6] + c2 * wc[7] + d2 * wc[8];
            a0 = c0; aa1 = c1; a2 = c2;
            c0 = d0; c1 = d1; c2 = d2;
        }
    }
    float* aggp = g_agg + row * 4096 + o * 1024 + ry * 32 + cx0;
    #pragma unroll
    for (int j = 0; j < 16; ++j)
        atomicAdd(aggp + j, fmaxf(acc2[j], 0.f));
}

// ---------------------------------------------------------------------------
// 3) transposed-conv upsample (unchanged)
// ---------------------------------------------------------------------------
__global__ __launch_bounds__(256) void k_up(const float* __restrict__ w,
                                            const float* __restrict__ b) {
    int idx = blockIdx.x * 256 + threadIdx.x;
    int n   = idx >> 14;
    int rem = idx & 16383;
    int o   = rem >> 12;
    int p   = rem & 4095;
    int y   = p >> 6;
    int xq  = p & 63;
    int i = y >> 1, j = xq >> 1, a = y & 1, bb = xq & 1;
    float v = __ldg(b + o);
    const float* ag = g_agg + n * 4096 + i * 32 + j;
    #pragma unroll
    for (int c = 0; c < 4; ++c)
        v += ag[c * 1024] * __ldg(w + (((c * 4 + o) * 2 + a) * 2 + bb));
    g_up[idx] = v;
}

// ---------------------------------------------------------------------------
// 4/5) direct 3x3 SAME conv via packed FFMA2.
//   Block: (32,4) = 128 threads, covers 8 rows x 32 cols x OCB out-channels.
//   blockIdx.y = (oblk << 3) | ytile.
//   SMEM: pre-packed weight pairs [OCB/2][CIN][9][2] + double-buffered tile.
//   Each thread: 8 rows x 4 channel-pairs = 32 f32x2 accumulators.
// ---------------------------------------------------------------------------
template <int CIN, int COUT, int OCB, bool RELU, bool CONCAT>
__global__ __launch_bounds__(128, 2)
void k_conv3x3(const float* __restrict__ in, const float* __restrict__ in2,
               const float* __restrict__ w, const float* __restrict__ bias,
               float* __restrict__ out) {
    extern __shared__ float sm[];
    float* sW = sm;                              // (OCB/2)*CIN*9*2 floats
    float* sT = sm + (OCB / 2) * CIN * 18;       // 2 x 344 floats

    const int n    = blockIdx.z;
    const int oblk = blockIdx.y >> 3;
    const int ty0  = (blockIdx.y & 7) * 8;
    const int tx0  = blockIdx.x * 32;
    const int tx   = threadIdx.x;                // 0..31
    const int og   = threadIdx.y;                // 0..3
    const int tid  = og * 32 + tx;

    // ---- copy + interleave weights for this block's OCB output channels ----
    const float* wg = w + (size_t)oblk * OCB * CIN * 9;
    for (int i = tid; i < OCB * CIN * 9; i += 128) {
        int o = i / (CIN * 9);
        int r = i - o * (CIN * 9);               // c*9 + t
        sW[((o >> 1) * (CIN * 9) + r) * 2 + (o & 1)] = __ldg(wg + i);
    }

    // ---- per-thread tile-load metadata (fixed across channels) ----
    constexpr int NLD = (340 + 127) / 128;       // 3
    int goff[NLD], soff[NLD];
    #pragma unroll
    for (int j = 0; j < NLD; ++j) {
        int i = tid + j * 128;
        if (i < 340) {
            int sy = i / 34, sx = i - sy * 34;
            int gy = ty0 + sy - 1, gx = tx0 + sx - 1;
            soff[j] = i;
            goff[j] = ((unsigned)gy < 64u && (unsigned)gx < 64u) ? gy * 64 + gx : -1;
        } else { soff[j] = -1; goff[j] = -1; }
    }

    // ---- init accumulators with packed bias ----
    ull acc[8][4];
    #pragma unroll
    for (int p = 0; p < 4; ++p) {
        int oc = oblk * OCB + og * 8 + 2 * p;
        ull bp = pk2(__ldg(bias + oc), __ldg(bias + oc + 1));
        #pragma unroll
        for (int r = 0; r < 8; ++r) acc[r][p] = bp;
    }

    // ---- prologue: stage channel 0 ----
    {
        const float* s;
        if (CONCAT) s = in + (size_t)n * 32 * 4096;           // c = 0 < 32
        else        s = in + (size_t)n * CIN * 4096;
        #pragma unroll
        for (int j = 0; j < NLD; ++j)
            if (soff[j] >= 0) sT[soff[j]] = (goff[j] >= 0) ? __ldg(s + goff[j]) : 0.f;
    }
    __syncthreads();

    // ---- main channel loop: 1 barrier / channel, dbl-buffered ----
    for (int c = 0; c < CIN; ++c) {
        const float* sbuf = sT + (c & 1) * 344;

        // prefetch channel c+1 into registers
        float pf[NLD];
        if (c + 1 < CIN) {
            const float* s;
            int cn = c + 1;
            if (CONCAT) s = (cn < 32) ? in  + ((size_t)n * 32 + cn) * 4096
                                      : in2 + ((size_t)n * 4 + (cn - 32)) * 4096;
            else        s = in + ((size_t)n * CIN + cn) * 4096;
            #pragma unroll
            for (int j = 0; j < NLD; ++j)
                pf[j] = (goff[j] >= 0) ? __ldg(s + goff[j]) : 0.f;
        }

        // weight pairs for this channel (ull units; pair stride = CIN*9)
        const ull* wp = reinterpret_cast<const ull*>(sW) + (og * 4) * (CIN * 9) + c * 9;

        #pragma unroll
        for (int dx = 0; dx < 3; ++dx) {
            ull vp[10];
            #pragma unroll
            for (int y = 0; y < 10; ++y) {
                float v = sbuf[y * 34 + tx + dx];
                vp[y] = pk2(v, v);
            }
            #pragma unroll
            for (int dy = 0; dy < 3; ++dy) {
                const int t = dy * 3 + dx;
                ull w0 = wp[0 * (CIN * 9) + t];
                ull w1 = wp[1 * (CIN * 9) + t];
                ull w2 = wp[2 * (CIN * 9) + t];
                ull w3 = wp[3 * (CIN * 9) + t];
                #pragma unroll
                for (int r = 0; r < 8; ++r) {
                    fma2(acc[r][0], vp[r + dy], w0);
                    fma2(acc[r][1], vp[r + dy], w1);
                    fma2(acc[r][2], vp[r + dy], w2);
                    fma2(acc[r][3], vp[r + dy], w3);
                }
            }
        }

        // commit prefetched channel to the other buffer
        if (c + 1 < CIN) {
            float* nb = sT + ((c + 1) & 1) * 344;
            #pragma unroll
            for (int j = 0; j < NLD; ++j)
                if (soff[j] >= 0) nb[soff[j]] = pf[j];
        }
        __syncthreads();
    }

    // ---- epilogue ----
    #pragma unroll
    for (int p = 0; p < 4; ++p) {
        int oc = oblk * OCB + og * 8 + 2 * p;
        float* o0 = out + (((size_t)n * COUT + oc) * 64 + ty0) * 64 + tx0 + tx;
        #pragma unroll
        for (int r = 0; r < 8; ++r) {
            float lo, hi;
            upk2(acc[r][p], lo, hi);
            if (RELU) { lo = fmaxf(lo, 0.f); hi = fmaxf(hi, 0.f); }
            o0[r * 64]        = lo;
            o0[4096 + r * 64] = hi;
        }
    }
}

// ---------------------------------------------------------------------------
extern "C" void kernel_launch(void* const* d_in, const int* in_sizes, int n_in,
                              void* d_out, int out_size) {
    const float* x      = (const float*)d_in[0];
    const int*   eidx   = (const int*)  d_in[1];
    const float* w_down = (const float*)d_in[3];
    const float* b_down = (const float*)d_in[4];
    const float* w_e1   = (const float*)d_in[5];
    const float* b_e1   = (const float*)d_in[6];
    const float* w_e2   = (const float*)d_in[7];
    const float* b_e2   = (const float*)d_in[8];
    const float* w_up   = (const float*)d_in[9];
    const float* b_up   = (const float*)d_in[10];
    const float* w_n1   = (const float*)d_in[11];
    const float* b_n1   = (const float*)d_in[12];
    const float* w_n2   = (const float*)d_in[13];
    const float* b_n2   = (const float*)d_in[14];
    float* out = (float*)d_out;

    float *up_ptr = nullptr, *hid_ptr = nullptr;
    cudaGetSymbolAddress((void**)&up_ptr,  g_up);
    cudaGetSymbolAddress((void**)&hid_ptr, g_hidden);

    // dynamic smem sizes: weights (OCB/2*CIN*9*2) + tile (2*344), floats
    const int sm1 = (16 * 36 * 9 * 2 + 2 * 344) * 4;   // 44224 B
    const int sm2 = (16 * 64 * 9 * 2 + 2 * 344) * 4;   // 76480 B
    cudaFuncSetAttribute((const void*)k_conv3x3<36, 64, 32, true, true>,
                         cudaFuncAttributeMaxDynamicSharedMemorySize, sm1);
    cudaFuncSetAttribute((const void*)k_conv3x3<64, 32, 32, false, false>,
                         cudaFuncAttributeMaxDynamicSharedMemorySize, sm2);

    // 1) downsample (also zeroes g_agg)
    k_down<<<1024, 256>>>(x, w_down, b_down);
    // 2) fused edge network + scatter-add
    k_edge<<<NEDGE, 256>>>(eidx, w_e1, b_e1, w_e2, b_e2);
    // 3) upsample
    k_up<<<16384, 256>>>(w_up, b_up);
    // 4) node conv1: concat(x, up) 36 -> 64, ReLU   (grid.y = 2 oblk * 8 ytiles)
    k_conv3x3<36, 64, 32, true, true><<<dim3(2, 16, 256), dim3(32, 4), sm1>>>(
        x, up_ptr, w_n1, b_n1, hid_ptr);
    // 5) node conv2: 64 -> 32                        (grid.y = 1 oblk * 8 ytiles)
    k_conv3x3<64, 32, 32, false, false><<<dim3(2, 8, 256), dim3(32, 4), sm2>>>(
        hid_ptr, nullptr, w_n2, b_n2, out);
}